// round 5
// baseline (speedup 1.0000x reference)
#include <cuda_runtime.h>
#include <cuda_bf16.h>
#include <math.h>
#include <stdint.h>

#define H 1024
#define I 2048
#define E 8
#define TOPK 2
#define T 4096   // B*S

// ======================= scratch (static device globals) =====================
__device__ __align__(256) int   g_counts[E];
__device__ __align__(256) float g_probsum[E];
__device__ float g_zsum;
__device__ __align__(256) int   g_list[E * T];
__device__ __align__(256) float g_wlist[E * T];

__device__ __align__(256) __nv_bfloat16 g_xh[(size_t)T * H];
__device__ __align__(256) __nv_bfloat16 g_xl[(size_t)T * H];
__device__ __align__(256) __nv_bfloat16 g_gth[(size_t)E * I * H];   // gate^T [e][i][h]
__device__ __align__(256) __nv_bfloat16 g_gtl[(size_t)E * I * H];
__device__ __align__(256) __nv_bfloat16 g_uth[(size_t)E * I * H];   // up^T
__device__ __align__(256) __nv_bfloat16 g_utl[(size_t)E * I * H];
__device__ __align__(256) __nv_bfloat16 g_dth[(size_t)E * H * I];   // down^T [e][h][i]
__device__ __align__(256) __nv_bfloat16 g_dtl[(size_t)E * H * I];
__device__ __align__(256) __nv_bfloat16 g_sgth[(size_t)I * H];
__device__ __align__(256) __nv_bfloat16 g_sgtl[(size_t)I * H];
__device__ __align__(256) __nv_bfloat16 g_suth[(size_t)I * H];
__device__ __align__(256) __nv_bfloat16 g_sutl[(size_t)I * H];
__device__ __align__(256) __nv_bfloat16 g_sdth[(size_t)H * I];
__device__ __align__(256) __nv_bfloat16 g_sdtl[(size_t)H * I];
__device__ __align__(256) __nv_bfloat16 g_acth[(size_t)(E + 1) * T * I];
__device__ __align__(256) __nv_bfloat16 g_actl[(size_t)(E + 1) * T * I];

// ======================= PTX helpers ========================================
static __device__ __forceinline__ uint32_t s2u(const void* p) {
    uint32_t a;
    asm("{ .reg .u64 t; cvta.to.shared.u64 t, %1; cvt.u32.u64 %0, t; }"
        : "=r"(a) : "l"(p));
    return a;
}
static __device__ __forceinline__ void ldsm_x4(uint32_t& r0, uint32_t& r1,
                                               uint32_t& r2, uint32_t& r3,
                                               uint32_t addr) {
    asm volatile("ldmatrix.sync.aligned.m8n8.x4.shared.b16 {%0,%1,%2,%3}, [%4];"
                 : "=r"(r0), "=r"(r1), "=r"(r2), "=r"(r3) : "r"(addr));
}
static __device__ __forceinline__ void mma_bf16(float* c, const uint32_t* a,
                                                uint32_t b0, uint32_t b1) {
    asm volatile(
        "mma.sync.aligned.m16n8k16.row.col.f32.bf16.bf16.f32 "
        "{%0,%1,%2,%3}, {%4,%5,%6,%7}, {%8,%9}, {%0,%1,%2,%3};"
        : "+f"(c[0]), "+f"(c[1]), "+f"(c[2]), "+f"(c[3])
        : "r"(a[0]), "r"(a[1]), "r"(a[2]), "r"(a[3]), "r"(b0), "r"(b1));
}
static __device__ __forceinline__ void cp16(uint32_t dst, const void* src,
                                            uint32_t sz) {
    asm volatile("cp.async.cg.shared.global [%0], [%1], 16, %2;"
                 :: "r"(dst), "l"(src), "r"(sz) : "memory");
}
#define CP_COMMIT() asm volatile("cp.async.commit_group;" ::: "memory")
#define CP_WAIT1()  asm volatile("cp.async.wait_group 1;" ::: "memory")
#define CP_WAIT0()  asm volatile("cp.async.wait_group 0;" ::: "memory")

// SW64 swizzle for 64-byte rows (8-row x 64B atom)
#define SWZ64(o) ((uint32_t)(o) ^ ((((uint32_t)(o)) >> 3) & 0x30u))

// ======================= SMEM layouts (per stage, 32 KB) =====================
#define GU_A_HI   0
#define GU_A_LO   8192
#define GU_BG_HI  16384
#define GU_BG_LO  20480
#define GU_BU_HI  24576
#define GU_BU_LO  28672
#define GU_STAGE  32768
#define GU_SMEM   (1024 + 3 * GU_STAGE)
#define DN_A_HI   0
#define DN_A_LO   8192
#define DN_B_HI   16384
#define DN_B_LO   24576
#define DN_STAGE  32768
#define DN_SMEM   (1024 + 3 * DN_STAGE)

// ======================= small kernels ======================================
__global__ void init_kernel() {
    int i = threadIdx.x;
    if (i < E) { g_counts[i] = 0; g_probsum[i] = 0.f; }
    if (i == 0) g_zsum = 0.f;
}

__global__ void router_convert_kernel(const float* __restrict__ x,
                                      const float* __restrict__ rw,
                                      float* __restrict__ out_logits) {
    const int tid = threadIdx.x;
    {
        size_t base = (size_t)blockIdx.x * 2048;
#pragma unroll
        for (int k = 0; k < 8; k++) {
            size_t i4 = base + tid + k * 256;
            float4 v = reinterpret_cast<const float4*>(x)[i4];
            size_t o = i4 * 4;
            __nv_bfloat16 h0 = __float2bfloat16(v.x), h1 = __float2bfloat16(v.y);
            __nv_bfloat16 h2 = __float2bfloat16(v.z), h3 = __float2bfloat16(v.w);
            __nv_bfloat162 ha, hb, la, lb;
            ha.x = h0; ha.y = h1; hb.x = h2; hb.y = h3;
            la.x = __float2bfloat16(v.x - __bfloat162float(h0));
            la.y = __float2bfloat16(v.y - __bfloat162float(h1));
            lb.x = __float2bfloat16(v.z - __bfloat162float(h2));
            lb.y = __float2bfloat16(v.w - __bfloat162float(h3));
            reinterpret_cast<__nv_bfloat162*>(g_xh + o)[0] = ha;
            reinterpret_cast<__nv_bfloat162*>(g_xh + o)[1] = hb;
            reinterpret_cast<__nv_bfloat162*>(g_xl + o)[0] = la;
            reinterpret_cast<__nv_bfloat162*>(g_xl + o)[1] = lb;
        }
    }
    int t = blockIdx.x * 8 + (tid >> 5);
    int lane = tid & 31;
    const float* xr = x + (size_t)t * H;

    float acc[E];
#pragma unroll
    for (int e = 0; e < E; e++) acc[e] = 0.f;
    for (int h = lane; h < H; h += 32) {
        float xv = xr[h];
        const float4* r4 = reinterpret_cast<const float4*>(rw + (size_t)h * E);
        float4 r0 = r4[0], r1 = r4[1];
        acc[0] += xv * r0.x; acc[1] += xv * r0.y;
        acc[2] += xv * r0.z; acc[3] += xv * r0.w;
        acc[4] += xv * r1.x; acc[5] += xv * r1.y;
        acc[6] += xv * r1.z; acc[7] += xv * r1.w;
    }
#pragma unroll
    for (int e = 0; e < E; e++)
#pragma unroll
        for (int off = 16; off > 0; off >>= 1)
            acc[e] += __shfl_xor_sync(0xffffffffu, acc[e], off);

    if (lane == 0) {
        float m = acc[0];
#pragma unroll
        for (int e = 1; e < E; e++) m = fmaxf(m, acc[e]);
        float p[E], s = 0.f;
#pragma unroll
        for (int e = 0; e < E; e++) { p[e] = expf(acc[e] - m); s += p[e]; }
        float inv = 1.f / s;
#pragma unroll
        for (int e = 0; e < E; e++) out_logits[(size_t)t * E + e] = acc[e];
        float lse = m + logf(s);
        atomicAdd(&g_zsum, lse * lse);
#pragma unroll
        for (int e = 0; e < E; e++) atomicAdd(&g_probsum[e], p[e] * inv);

        int e1 = 0;
#pragma unroll
        for (int e = 1; e < E; e++) if (acc[e] > acc[e1]) e1 = e;
        int e2 = (e1 == 0) ? 1 : 0;
#pragma unroll
        for (int e = 0; e < E; e++) if (e != e1 && acc[e] > acc[e2]) e2 = e;
        float p1 = p[e1] * inv, p2 = p[e2] * inv;
        float wn = 1.f / (p1 + p2);
        int pos1 = atomicAdd(&g_counts[e1], 1);
        g_list[e1 * T + pos1] = t;  g_wlist[e1 * T + pos1] = p1 * wn;
        int pos2 = atomicAdd(&g_counts[e2], 1);
        g_list[e2 * T + pos2] = t;  g_wlist[e2 * T + pos2] = p2 * wn;
    }
}

__global__ void finalize_kernel(float* __restrict__ out) {
    if (threadIdx.x == 0) {
        float aux = 0.f;
#pragma unroll
        for (int e = 0; e < E; e++) {
            float tpe = (float)g_counts[e] / (float)(TOPK * T);
            float ppe = g_probsum[e] / (float)T;
            aux += tpe * ppe;
        }
        out[(size_t)T * H]     = (float)E * aux;
        out[(size_t)T * H + 1] = g_zsum / (float)T;
    }
}

__global__ void transpose_all_kernel(const float* __restrict__ gw,
                                     const float* __restrict__ uw,
                                     const float* __restrict__ dw,
                                     const float* __restrict__ sgw,
                                     const float* __restrict__ suw,
                                     const float* __restrict__ sdw) {
    const int z = blockIdx.z;
    int which, ex;
    if (z < 8)       { which = 0; ex = z; }
    else if (z < 16) { which = 1; ex = z - 8; }
    else if (z < 24) { which = 2; ex = z - 16; }
    else             { which = z - 21; ex = 0; }

    int R, C;
    const float* src;
    __nv_bfloat16 *oh, *ol;
    switch (which) {
        case 0: R = H; C = I; src = gw;  oh = g_gth;  ol = g_gtl;  break;
        case 1: R = H; C = I; src = uw;  oh = g_uth;  ol = g_utl;  break;
        case 2: R = I; C = H; src = dw;  oh = g_dth;  ol = g_dtl;  break;
        case 3: R = H; C = I; src = sgw; oh = g_sgth; ol = g_sgtl; break;
        case 4: R = H; C = I; src = suw; oh = g_suth; ol = g_sutl; break;
        default: R = I; C = H; src = sdw; oh = g_sdth; ol = g_sdtl; break;
    }
    if ((int)blockIdx.x * 32 >= C || (int)blockIdx.y * 32 >= R) return;
    size_t zoff = (size_t)ex * R * C;
    src += zoff; oh += zoff; ol += zoff;

    __shared__ float tile[32][33];
    int c0 = blockIdx.x * 32, r0 = blockIdx.y * 32;
    int tx = threadIdx.x, ty = threadIdx.y;
#pragma unroll
    for (int i = 0; i < 4; i++)
        tile[ty + i * 8][tx] = src[(size_t)(r0 + ty + i * 8) * C + c0 + tx];
    __syncthreads();
#pragma unroll
    for (int i = 0; i < 4; i++) {
        float v = tile[tx][ty + i * 8];
        __nv_bfloat16 h = __float2bfloat16(v);
        size_t di = (size_t)(c0 + ty + i * 8) * R + r0 + tx;
        oh[di] = h;
        ol[di] = __float2bfloat16(v - __bfloat162float(h));
    }
}

// ======================= GEMM 1: gate+up (HMMA bf16x3) =======================
__global__ void __launch_bounds__(256, 2) mm_gateup_kernel() {
    extern __shared__ char smem[];
    const int e = blockIdx.z;
    const int cnt = (e < E) ? g_counts[e] : T;
    const int m0 = blockIdx.y * 128;
    if (m0 >= cnt) return;
    const int n0 = blockIdx.x * 64;
    const int tid = threadIdx.x;
    const int wid = tid >> 5;
    const int lane = tid & 31;

    int* rowTok = (int*)smem;
    if (tid < 128) {
        int slot = m0 + tid;
        rowTok[tid] = (slot < cnt) ? ((e < E) ? g_list[e * T + slot] : slot) : -1;
    }
    __syncthreads();

    const uint32_t sb = s2u(smem) + 1024;

    const __nv_bfloat16* Gh = (e < E) ? g_gth + (size_t)e * I * H : g_sgth;
    const __nv_bfloat16* Gl = (e < E) ? g_gtl + (size_t)e * I * H : g_sgtl;
    const __nv_bfloat16* Uh = (e < E) ? g_uth + (size_t)e * I * H : g_suth;
    const __nv_bfloat16* Ul = (e < E) ? g_utl + (size_t)e * I * H : g_sutl;

    const int u4 = tid & 3;
    const int rb = tid >> 2;

    // hoisted load addressing
    const int tok0 = rowTok[rb];
    const int tok1 = rowTok[rb + 64];
    const size_t aG0 = (size_t)(tok0 >= 0 ? tok0 : 0) * H + u4 * 8;
    const size_t aG1 = (size_t)(tok1 >= 0 ? tok1 : 0) * H + u4 * 8;
    const uint32_t sz0 = (tok0 >= 0) ? 16u : 0u;
    const uint32_t sz1 = (tok1 >= 0) ? 16u : 0u;
    const size_t bG  = (size_t)(n0 + rb) * H + u4 * 8;
    const uint32_t dA0 = SWZ64(rb * 64 + u4 * 16);
    const uint32_t dA1 = SWZ64((rb + 64) * 64 + u4 * 16);

    auto load_stage = [&](int st, int c) {
        const int k0 = c * 32;
        const uint32_t bp = sb + st * GU_STAGE;
        cp16(bp + GU_A_HI + dA0, g_xh + aG0 + k0, sz0);
        cp16(bp + GU_A_LO + dA0, g_xl + aG0 + k0, sz0);
        cp16(bp + GU_A_HI + dA1, g_xh + aG1 + k0, sz1);
        cp16(bp + GU_A_LO + dA1, g_xl + aG1 + k0, sz1);
        cp16(bp + GU_BG_HI + dA0, Gh + bG + k0, 16);
        cp16(bp + GU_BG_LO + dA0, Gl + bG + k0, 16);
        cp16(bp + GU_BU_HI + dA0, Uh + bG + k0, 16);
        cp16(bp + GU_BU_LO + dA0, Ul + bG + k0, 16);
    };

    float accG[4][2][4], accU[4][2][4];
#pragma unroll
    for (int i = 0; i < 4; i++)
#pragma unroll
        for (int j = 0; j < 2; j++)
#pragma unroll
            for (int q = 0; q < 4; q++) { accG[i][j][q] = 0.f; accU[i][j][q] = 0.f; }

    const int mw = (wid & 1) * 64;
    const int nw = (wid >> 1) * 16;
    const int arow_off = ((lane >> 3) & 1) * 8 + (lane & 7);
    const int akb_off = (lane >> 4) * 16;
    const int brow = nw + (lane & 15);
    const int bkb_off = (lane >> 4) * 16;

    // hoisted ldsm offsets
    uint32_t aoff[4][2], boff[2];
#pragma unroll
    for (int i = 0; i < 4; i++)
#pragma unroll
        for (int kk = 0; kk < 2; kk++)
            aoff[i][kk] = SWZ64((mw + i * 16 + arow_off) * 64 + kk * 32 + akb_off);
#pragma unroll
    for (int kk = 0; kk < 2; kk++)
        boff[kk] = SWZ64(brow * 64 + kk * 32 + bkb_off);

    auto compute_stage = [&](int st) {
        const uint32_t bp = sb + st * GU_STAGE;
#pragma unroll
        for (int kk = 0; kk < 2; kk++) {
            uint32_t a[4][4];
            uint32_t gh[4], gl[4], uh[4], ul[4];
            ldsm_x4(gh[0], gh[1], gh[2], gh[3], bp + GU_BG_HI + boff[kk]);
            ldsm_x4(gl[0], gl[1], gl[2], gl[3], bp + GU_BG_LO + boff[kk]);
            ldsm_x4(uh[0], uh[1], uh[2], uh[3], bp + GU_BU_HI + boff[kk]);
            ldsm_x4(ul[0], ul[1], ul[2], ul[3], bp + GU_BU_LO + boff[kk]);
#pragma unroll
            for (int i = 0; i < 4; i++)
                ldsm_x4(a[i][0], a[i][1], a[i][2], a[i][3], bp + GU_A_HI + aoff[i][kk]);
            // term-major passes: same accumulator revisited at distance 8
#pragma unroll
            for (int i = 0; i < 4; i++) {
                mma_bf16(accG[i][0], a[i], gh[0], gh[2]);
                mma_bf16(accG[i][1], a[i], gh[1], gh[3]);
            }
#pragma unroll
            for (int i = 0; i < 4; i++) {
                mma_bf16(accU[i][0], a[i], uh[0], uh[2]);
                mma_bf16(accU[i][1], a[i], uh[1], uh[3]);
            }
#pragma unroll
            for (int i = 0; i < 4; i++) {
                mma_bf16(accG[i][0], a[i], gl[0], gl[2]);
                mma_bf16(accG[i][1], a[i], gl[1], gl[3]);
            }
#pragma unroll
            for (int i = 0; i < 4; i++) {
                mma_bf16(accU[i][0], a[i], ul[0], ul[2]);
                mma_bf16(accU[i][1], a[i], ul[1], ul[3]);
            }
#pragma unroll
            for (int i = 0; i < 4; i++)
                ldsm_x4(a[i][0], a[i][1], a[i][2], a[i][3], bp + GU_A_LO + aoff[i][kk]);
#pragma unroll
            for (int i = 0; i < 4; i++) {
                mma_bf16(accG[i][0], a[i], gh[0], gh[2]);
                mma_bf16(accG[i][1], a[i], gh[1], gh[3]);
            }
#pragma unroll
            for (int i = 0; i < 4; i++) {
                mma_bf16(accU[i][0], a[i], uh[0], uh[2]);
                mma_bf16(accU[i][1], a[i], uh[1], uh[3]);
            }
        }
    };

    const int NC = H / 32;
    load_stage(0, 0); CP_COMMIT();
    load_stage(1, 1); CP_COMMIT();
    int st = 0;
    for (int c = 0; c < NC; c++) {
        if (c < NC - 1) CP_WAIT1(); else CP_WAIT0();
        __syncthreads();
        if (c + 2 < NC) {
            int ls = st + 2; if (ls >= 3) ls -= 3;
            load_stage(ls, c + 2); CP_COMMIT();
        }
        compute_stage(st);
        if (++st == 3) st = 0;
    }

    const int r4 = lane >> 2;
    const int cp2 = (lane & 3) * 2;
#pragma unroll
    for (int i = 0; i < 4; i++)
#pragma unroll
        for (int hh = 0; hh < 2; hh++) {
            int slot = m0 + mw + i * 16 + r4 + hh * 8;
            if (slot >= cnt) continue;
#pragma unroll
            for (int j = 0; j < 2; j++) {
                float g0 = accG[i][j][hh * 2 + 0], g1 = accG[i][j][hh * 2 + 1];
                float u0 = accU[i][j][hh * 2 + 0], u1 = accU[i][j][hh * 2 + 1];
                float v0 = g0 / (1.f + __expf(-g0)) * u0;
                float v1 = g1 / (1.f + __expf(-g1)) * u1;
                __nv_bfloat16 h0 = __float2bfloat16(v0), h1 = __float2bfloat16(v1);
                __nv_bfloat162 hp; hp.x = h0; hp.y = h1;
                __nv_bfloat162 lp;
                lp.x = __float2bfloat16(v0 - __bfloat162float(h0));
                lp.y = __float2bfloat16(v1 - __bfloat162float(h1));
                size_t ai = (size_t)e * T * I + (size_t)slot * I + n0 + nw + j * 8 + cp2;
                *reinterpret_cast<__nv_bfloat162*>(g_acth + ai) = hp;
                *reinterpret_cast<__nv_bfloat162*>(g_actl + ai) = lp;
            }
        }
}

// ======================= GEMM 2: down (HMMA bf16x3) ==========================
template <bool SHARED_E>
__global__ void __launch_bounds__(256, 2) mm_down_kernel(float* __restrict__ out) {
    extern __shared__ char smem[];
    const int e  = SHARED_E ? 0 : blockIdx.z;
    const int ea = SHARED_E ? E : blockIdx.z;
    const int cnt = SHARED_E ? T : g_counts[e];
    const int m0 = blockIdx.y * 128;
    if (m0 >= cnt) return;
    const int n0 = blockIdx.x * 128;
    const int tid = threadIdx.x;
    const int wid = tid >> 5;
    const int lane = tid & 31;

    int* tokSm = (int*)smem;
    float* wSm = (float*)(smem + 512);
    if (!SHARED_E && tid < 128) {
        int slot = m0 + tid;
        tokSm[tid] = (slot < cnt) ? g_list[e * T + slot] : 0;
        wSm[tid]   = (slot < cnt) ? g_wlist[e * T + slot] : 0.f;
    }
    __syncthreads();

    const uint32_t sb = s2u(smem) + 1024;

    const __nv_bfloat16* Bh = SHARED_E ? g_sdth : g_dth + (size_t)e * H * I;
    const __nv_bfloat16* Bl = SHARED_E ? g_sdtl : g_dtl + (size_t)e * H * I;
    const __nv_bfloat16* Ah = g_acth + (size_t)ea * T * I;
    const __nv_bfloat16* Al = g_actl + (size_t)ea * T * I;

    const int u4 = tid & 3;
    const int rb = tid >> 2;

    const int slot0 = m0 + rb;
    const int slot1 = m0 + rb + 64;
    const size_t aO0 = (size_t)(slot0 < cnt ? slot0 : 0) * I + u4 * 8;
    const size_t aO1 = (size_t)(slot1 < cnt ? slot1 : 0) * I + u4 * 8;
    const uint32_t sz0 = (slot0 < cnt) ? 16u : 0u;
    const uint32_t sz1 = (slot1 < cnt) ? 16u : 0u;
    const size_t bO0 = (size_t)(n0 + rb) * I + u4 * 8;
    const size_t bO1 = (size_t)(n0 + rb + 64) * I + u4 * 8;
    const uint32_t dA0 = SWZ64(rb * 64 + u4 * 16);
    const uint32_t dA1 = SWZ64((rb + 64) * 64 + u4 * 16);

    auto load_stage = [&](int st, int c) {
        const int k0 = c * 32;
        const uint32_t bp = sb + st * DN_STAGE;
        cp16(bp + DN_A_HI + dA0, Ah + aO0 + k0, sz0);
        cp16(bp + DN_A_LO + dA0, Al + aO0 + k0, sz0);
        cp16(bp + DN_A_HI + dA1, Ah + aO1 + k0, sz1);
        cp16(bp + DN_A_LO + dA1, Al + aO1 + k0, sz1);
        cp16(bp + DN_B_HI + dA0, Bh + bO0 + k0, 16);
        cp16(bp + DN_B_LO + dA0, Bl + bO0 + k0, 16);
        cp16(bp + DN_B_HI + dA1, Bh + bO1 + k0, 16);
        cp16(bp + DN_B_LO + dA1, Bl + bO1 + k0, 16);
    };

    float acc[4][4][4];
#pragma unroll
    for (int i = 0; i < 4; i++)
#pragma unroll
        for (int j = 0; j < 4; j++)
#pragma unroll
            for (int q = 0; q < 4; q++) acc[i][j][q] = 0.f;

    const int mw = (wid & 1) * 64;
    const int nw = (wid >> 1) * 32;
    const int arow_off = ((lane >> 3) & 1) * 8 + (lane & 7);
    const int akb_off = (lane >> 4) * 16;
    const int bl16 = lane & 15;
    const int bkb_off = (lane >> 4) * 16;

    uint32_t aoff[4][2], boff[2][2];
#pragma unroll
    for (int i = 0; i < 4; i++)
#pragma unroll
        for (int kk = 0; kk < 2; kk++)
            aoff[i][kk] = SWZ64((mw + i * 16 + arow_off) * 64 + kk * 32 + akb_off);
#pragma unroll
    for (int jp = 0; jp < 2; jp++)
#pragma unroll
        for (int kk = 0; kk < 2; kk++)
            boff[jp][kk] = SWZ64((nw + jp * 16 + bl16) * 64 + kk * 32 + bkb_off);

    auto compute_stage = [&](int st) {
        const uint32_t bp = sb + st * DN_STAGE;
#pragma unroll
        for (int kk = 0; kk < 2; kk++) {
            uint32_t a[4][4];
            uint32_t bh[2][4], bl[2][4];
#pragma unroll
            for (int jp = 0; jp < 2; jp++) {
                ldsm_x4(bh[jp][0], bh[jp][1], bh[jp][2], bh[jp][3], bp + DN_B_HI + boff[jp][kk]);
                ldsm_x4(bl[jp][0], bl[jp][1], bl[jp][2], bl[jp][3], bp + DN_B_LO + boff[jp][kk]);
            }
#pragma unroll
            for (int i = 0; i < 4; i++)
                ldsm_x4(a[i][0], a[i][1], a[i][2], a[i][3], bp + DN_A_HI + aoff[i][kk]);
            // pass 1: A-hi x B-hi (each acc once -> distance 16)
#pragma unroll
            for (int i = 0; i < 4; i++)
#pragma unroll
                for (int jp = 0; jp < 2; jp++) {
                    mma_bf16(acc[i][jp * 2 + 0], a[i], bh[jp][0], bh[jp][2]);
                    mma_bf16(acc[i][jp * 2 + 1], a[i], bh[jp][1], bh[jp][3]);
                }
            // pass 2: A-hi x B-lo
#pragma unroll
            for (int i = 0; i < 4; i++)
#pragma unroll
                for (int jp = 0; jp < 2; jp++) {
                    mma_bf16(acc[i][jp * 2 + 0], a[i], bl[jp][0], bl[jp][2]);
                    mma_bf16(acc[i][jp * 2 + 1], a[i], bl[jp][1], bl[jp][3]);
                }
#pragma unroll
            for (int i = 0; i < 4; i++)
                ldsm_x4(a[i][0], a[i][1], a[i][2], a[i][3], bp + DN_A_LO + aoff[i][kk]);
            // pass 3: A-lo x B-hi
#pragma unroll
            for (int i = 0; i < 4; i++)
#pragma unroll
                for (int jp = 0; jp < 2; jp++) {
                    mma_bf16(acc[i][jp * 2 + 0], a[i], bh[jp][0], bh[jp][2]);
                    mma_bf16(acc[i][jp * 2 + 1], a[i], bh[jp][1], bh[jp][3]);
                }
        }
    };

    const int NC = I / 32;
    load_stage(0, 0); CP_COMMIT();
    load_stage(1, 1); CP_COMMIT();
    int st = 0;
    for (int c = 0; c < NC; c++) {
        if (c < NC - 1) CP_WAIT1(); else CP_WAIT0();
        __syncthreads();
        if (c + 2 < NC) {
            int ls = st + 2; if (ls >= 3) ls -= 3;
            load_stage(ls, c + 2); CP_COMMIT();
        }
        compute_stage(st);
        if (++st == 3) st = 0;
    }

    const int r4 = lane >> 2;
    const int cp2 = (lane & 3) * 2;
#pragma unroll
    for (int i = 0; i < 4; i++)
#pragma unroll
        for (int hh = 0; hh < 2; hh++) {
            int row = mw + i * 16 + r4 + hh * 8;
            int slot = m0 + row;
            if (slot >= cnt) continue;
#pragma unroll
            for (int j = 0; j < 4; j++) {
                float v0 = acc[i][j][hh * 2 + 0];
                float v1 = acc[i][j][hh * 2 + 1];
                int col = n0 + nw + j * 8 + cp2;
                if (SHARED_E) {
                    float2* dst = reinterpret_cast<float2*>(out + (size_t)slot * H + col);
                    *dst = make_float2(v0, v1);
                } else {
                    int tok = tokSm[row];
                    float w = wSm[row];
                    float* dst = out + (size_t)tok * H + col;
                    atomicAdd(&dst[0], w * v0);
                    atomicAdd(&dst[1], w * v1);
                }
            }
        }
}

// ======================= launch =============================================
extern "C" void kernel_launch(void* const* d_in, const int* in_sizes, int n_in,
                              void* d_out, int out_size) {
    const float* x   = (const float*)d_in[0];
    const float* rw  = (const float*)d_in[1];
    const float* gw  = (const float*)d_in[2];
    const float* uw  = (const float*)d_in[3];
    const float* dw  = (const float*)d_in[4];
    const float* sgw = (const float*)d_in[5];
    const float* suw = (const float*)d_in[6];
    const float* sdw = (const float*)d_in[7];
    float* out = (float*)d_out;

    cudaFuncSetAttribute(mm_gateup_kernel,
                         cudaFuncAttributeMaxDynamicSharedMemorySize, GU_SMEM);
    cudaFuncSetAttribute(mm_down_kernel<true>,
                         cudaFuncAttributeMaxDynamicSharedMemorySize, DN_SMEM);
    cudaFuncSetAttribute(mm_down_kernel<false>,
                         cudaFuncAttributeMaxDynamicSharedMemorySize, DN_SMEM);

    init_kernel<<<1, 32>>>();
    router_convert_kernel<<<T / 8, 256>>>(x, rw, out + (size_t)T * H + 2);
    transpose_all_kernel<<<dim3(64, 64, 27), dim3(32, 8)>>>(gw, uw, dw, sgw, suw, sdw);
    mm_gateup_kernel<<<dim3(I / 64, T / 128, E + 1), 256, GU_SMEM>>>();
    mm_down_kernel<true><<<dim3(H / 128, T / 128, 1), 256, DN_SMEM>>>(out);
    mm_down_kernel<false><<<dim3(H / 128, T / 128, E), 256, DN_SMEM>>>(out);
    finalize_kernel<<<1, 32>>>(out);
}

// round 6
// speedup vs baseline: 1.2044x; 1.2044x over previous
#include <cuda_runtime.h>
#include <cuda_bf16.h>
#include <math.h>
#include <stdint.h>

#define H 1024
#define I 2048
#define E 8
#define TOPK 2
#define T 4096   // B*S

// ======================= scratch (static device globals) =====================
__device__ __align__(256) int   g_counts[E];
__device__ __align__(256) float g_probsum[E];
__device__ float g_zsum;
__device__ __align__(256) int   g_list[E * T];
__device__ __align__(256) float g_wlist[E * T];

// bf16 hi/lo splits, all in NATURAL [K][N] layout (no transpose)
__device__ __align__(256) __nv_bfloat16 g_xh[(size_t)T * H];
__device__ __align__(256) __nv_bfloat16 g_xl[(size_t)T * H];
__device__ __align__(256) __nv_bfloat16 g_gh[(size_t)E * H * I];
__device__ __align__(256) __nv_bfloat16 g_gl[(size_t)E * H * I];
__device__ __align__(256) __nv_bfloat16 g_uh[(size_t)E * H * I];
__device__ __align__(256) __nv_bfloat16 g_ul[(size_t)E * H * I];
__device__ __align__(256) __nv_bfloat16 g_dh[(size_t)E * I * H];
__device__ __align__(256) __nv_bfloat16 g_dl[(size_t)E * I * H];
__device__ __align__(256) __nv_bfloat16 g_sgh[(size_t)H * I];
__device__ __align__(256) __nv_bfloat16 g_sgl[(size_t)H * I];
__device__ __align__(256) __nv_bfloat16 g_suh[(size_t)H * I];
__device__ __align__(256) __nv_bfloat16 g_sul[(size_t)H * I];
__device__ __align__(256) __nv_bfloat16 g_sdh[(size_t)I * H];
__device__ __align__(256) __nv_bfloat16 g_sdl[(size_t)I * H];
__device__ __align__(256) __nv_bfloat16 g_acth[(size_t)(E + 1) * T * I];
__device__ __align__(256) __nv_bfloat16 g_actl[(size_t)(E + 1) * T * I];

// ======================= PTX helpers ========================================
static __device__ __forceinline__ uint32_t s2u(const void* p) {
    uint32_t a;
    asm("{ .reg .u64 t; cvta.to.shared.u64 t, %1; cvt.u32.u64 %0, t; }"
        : "=r"(a) : "l"(p));
    return a;
}
static __device__ __forceinline__ void ldsm_x4(uint32_t& r0, uint32_t& r1,
                                               uint32_t& r2, uint32_t& r3,
                                               uint32_t addr) {
    asm volatile("ldmatrix.sync.aligned.m8n8.x4.shared.b16 {%0,%1,%2,%3}, [%4];"
                 : "=r"(r0), "=r"(r1), "=r"(r2), "=r"(r3) : "r"(addr));
}
static __device__ __forceinline__ void ldsm_x4t(uint32_t& r0, uint32_t& r1,
                                                uint32_t& r2, uint32_t& r3,
                                                uint32_t addr) {
    asm volatile("ldmatrix.sync.aligned.m8n8.x4.trans.shared.b16 {%0,%1,%2,%3}, [%4];"
                 : "=r"(r0), "=r"(r1), "=r"(r2), "=r"(r3) : "r"(addr));
}
static __device__ __forceinline__ void mma_bf16(float* c, const uint32_t* a,
                                                uint32_t b0, uint32_t b1) {
    asm volatile(
        "mma.sync.aligned.m16n8k16.row.col.f32.bf16.bf16.f32 "
        "{%0,%1,%2,%3}, {%4,%5,%6,%7}, {%8,%9}, {%0,%1,%2,%3};"
        : "+f"(c[0]), "+f"(c[1]), "+f"(c[2]), "+f"(c[3])
        : "r"(a[0]), "r"(a[1]), "r"(a[2]), "r"(a[3]), "r"(b0), "r"(b1));
}
static __device__ __forceinline__ void cp16(uint32_t dst, const void* src,
                                            uint32_t sz) {
    asm volatile("cp.async.cg.shared.global [%0], [%1], 16, %2;"
                 :: "r"(dst), "l"(src), "r"(sz) : "memory");
}
#define CP_COMMIT() asm volatile("cp.async.commit_group;" ::: "memory")
#define CP_WAIT1()  asm volatile("cp.async.wait_group 1;" ::: "memory")
#define CP_WAIT0()  asm volatile("cp.async.wait_group 0;" ::: "memory")

#define SWZ64(o)  ((uint32_t)(o) ^ ((((uint32_t)(o)) >> 3) & 0x30u))
#define SWZ128(o) ((uint32_t)(o) ^ ((((uint32_t)(o)) >> 3) & 0x70u))

// ======================= SMEM layouts (per stage) ===========================
// gateup stage 32KB: A_hi 8K | A_lo 8K | Bg_hi 4K | Bg_lo 4K | Bu_hi 4K | Bu_lo 4K
#define GU_A_HI   0
#define GU_A_LO   8192
#define GU_BG_HI  16384
#define GU_BG_LO  20480
#define GU_BU_HI  24576
#define GU_BU_LO  28672
#define GU_STAGE  32768
#define GU_SMEM   (1024 + 3 * GU_STAGE)
// down stage 24KB: A_hi 8K | A_lo 8K | B_hi 4K | B_lo 4K   (N=64)
#define DN_A_HI   0
#define DN_A_LO   8192
#define DN_B_HI   16384
#define DN_B_LO   20480
#define DN_STAGE  24576
#define DN_SMEM   (1024 + 3 * DN_STAGE)

// ======================= init / finalize ====================================
__global__ void init_kernel() {
    int i = threadIdx.x;
    if (i < E) { g_counts[i] = 0; g_probsum[i] = 0.f; }
    if (i == 0) g_zsum = 0.f;
}

__global__ void finalize_kernel(float* __restrict__ out) {
    if (threadIdx.x == 0) {
        float aux = 0.f;
#pragma unroll
        for (int e = 0; e < E; e++) {
            float tpe = (float)g_counts[e] / (float)(TOPK * T);
            float ppe = g_probsum[e] / (float)T;
            aux += tpe * ppe;
        }
        out[(size_t)T * H]     = (float)E * aux;
        out[(size_t)T * H + 1] = g_zsum / (float)T;
    }
}

// ======================= prep: router + x-split + out-zero + weight-split ====
static __device__ __forceinline__ void split_store(const float4 v,
                                                   __nv_bfloat16* dh,
                                                   __nv_bfloat16* dl, size_t o) {
    __nv_bfloat16 h0 = __float2bfloat16(v.x), h1 = __float2bfloat16(v.y);
    __nv_bfloat16 h2 = __float2bfloat16(v.z), h3 = __float2bfloat16(v.w);
    __nv_bfloat162 ha, hb, la, lb;
    ha.x = h0; ha.y = h1; hb.x = h2; hb.y = h3;
    la.x = __float2bfloat16(v.x - __bfloat162float(h0));
    la.y = __float2bfloat16(v.y - __bfloat162float(h1));
    lb.x = __float2bfloat16(v.z - __bfloat162float(h2));
    lb.y = __float2bfloat16(v.w - __bfloat162float(h3));
    reinterpret_cast<__nv_bfloat162*>(dh + o)[0] = ha;
    reinterpret_cast<__nv_bfloat162*>(dh + o)[1] = hb;
    reinterpret_cast<__nv_bfloat162*>(dl + o)[0] = la;
    reinterpret_cast<__nv_bfloat162*>(dl + o)[1] = lb;
}

#define GW4 ((size_t)E * H * I / 4)      // 4194304
#define SW4 ((size_t)H * I / 4)          // 524288
#define WTOT4 (3 * GW4 + 3 * SW4)        // 14155776
#define NROUTER 512
#define NWBLK (WTOT4 / 512)              // 27648

__global__ void prep_kernel(const float* __restrict__ x,
                            const float* __restrict__ rw,
                            const float* __restrict__ gw,
                            const float* __restrict__ uw,
                            const float* __restrict__ dw,
                            const float* __restrict__ sgw,
                            const float* __restrict__ suw,
                            const float* __restrict__ sdw,
                            float* __restrict__ out) {
    const int b = blockIdx.x;
    const int tid = threadIdx.x;

    if (b >= NROUTER) {
        // ---- weight split: 512 float4 per block ----
        size_t base = (size_t)(b - NROUTER) * 512 + tid;
#pragma unroll
        for (int r = 0; r < 2; r++) {
            size_t i4 = base + r * 256;
            const float* src; __nv_bfloat16 *dh, *dl; size_t loc;
            if (i4 < GW4)                { src = gw;  dh = g_gh;  dl = g_gl;  loc = i4; }
            else if (i4 < 2 * GW4)       { src = uw;  dh = g_uh;  dl = g_ul;  loc = i4 - GW4; }
            else if (i4 < 3 * GW4)       { src = dw;  dh = g_dh;  dl = g_dl;  loc = i4 - 2 * GW4; }
            else if (i4 < 3 * GW4 + SW4) { src = sgw; dh = g_sgh; dl = g_sgl; loc = i4 - 3 * GW4; }
            else if (i4 < 3 * GW4 + 2 * SW4) { src = suw; dh = g_suh; dl = g_sul; loc = i4 - 3 * GW4 - SW4; }
            else                         { src = sdw; dh = g_sdh; dl = g_sdl; loc = i4 - 3 * GW4 - 2 * SW4; }
            float4 v = reinterpret_cast<const float4*>(src)[loc];
            split_store(v, dh, dl, loc * 4);
        }
        return;
    }

    // ---- x-split for this block's 8 tokens ----
    {
        size_t base = (size_t)b * 2048;
#pragma unroll
        for (int k = 0; k < 8; k++) {
            size_t i4 = base + tid + k * 256;
            float4 v = reinterpret_cast<const float4*>(x)[i4];
            split_store(v, g_xh, g_xl, i4 * 4);
        }
    }
    // ---- zero out rows for these 8 tokens ----
    {
        float4 z4 = make_float4(0.f, 0.f, 0.f, 0.f);
        size_t base = (size_t)b * 2048;
#pragma unroll
        for (int k = 0; k < 8; k++)
            reinterpret_cast<float4*>(out)[base + tid + k * 256] = z4;
    }
    // ---- router ----
    int t = b * 8 + (tid >> 5);
    int lane = tid & 31;
    const float* xr = x + (size_t)t * H;
    float* out_logits = out + (size_t)T * H + 2;

    float acc[E];
#pragma unroll
    for (int e = 0; e < E; e++) acc[e] = 0.f;
    for (int h = lane; h < H; h += 32) {
        float xv = xr[h];
        const float4* r4 = reinterpret_cast<const float4*>(rw + (size_t)h * E);
        float4 r0 = r4[0], r1 = r4[1];
        acc[0] += xv * r0.x; acc[1] += xv * r0.y;
        acc[2] += xv * r0.z; acc[3] += xv * r0.w;
        acc[4] += xv * r1.x; acc[5] += xv * r1.y;
        acc[6] += xv * r1.z; acc[7] += xv * r1.w;
    }
#pragma unroll
    for (int e = 0; e < E; e++)
#pragma unroll
        for (int off = 16; off > 0; off >>= 1)
            acc[e] += __shfl_xor_sync(0xffffffffu, acc[e], off);

    if (lane == 0) {
        float m = acc[0];
#pragma unroll
        for (int e = 1; e < E; e++) m = fmaxf(m, acc[e]);
        float p[E], s = 0.f;
#pragma unroll
        for (int e = 0; e < E; e++) { p[e] = expf(acc[e] - m); s += p[e]; }
        float inv = 1.f / s;
#pragma unroll
        for (int e = 0; e < E; e++) out_logits[(size_t)t * E + e] = acc[e];
        float lse = m + logf(s);
        atomicAdd(&g_zsum, lse * lse);
#pragma unroll
        for (int e = 0; e < E; e++) atomicAdd(&g_probsum[e], p[e] * inv);

        int e1 = 0;
#pragma unroll
        for (int e = 1; e < E; e++) if (acc[e] > acc[e1]) e1 = e;
        int e2 = (e1 == 0) ? 1 : 0;
#pragma unroll
        for (int e = 0; e < E; e++) if (e != e1 && acc[e] > acc[e2]) e2 = e;
        float p1 = p[e1] * inv, p2 = p[e2] * inv;
        float wn = 1.f / (p1 + p2);
        int pos1 = atomicAdd(&g_counts[e1], 1);
        g_list[e1 * T + pos1] = t;  g_wlist[e1 * T + pos1] = p1 * wn;
        int pos2 = atomicAdd(&g_counts[e2], 1);
        g_list[e2 * T + pos2] = t;  g_wlist[e2 * T + pos2] = p2 * wn;
    }
}

// ======================= GEMM 1: gate+up (HMMA bf16x3, B via ldsm.trans) =====
__global__ void __launch_bounds__(256, 2) mm_gateup_kernel() {
    extern __shared__ char smem[];
    const int e = blockIdx.z;
    const int cnt = (e < E) ? g_counts[e] : T;
    const int m0 = blockIdx.y * 128;
    if (m0 >= cnt) return;
    const int n0 = blockIdx.x * 64;
    const int tid = threadIdx.x;
    const int wid = tid >> 5;
    const int lane = tid & 31;

    int* rowTok = (int*)smem;
    if (tid < 128) {
        int slot = m0 + tid;
        rowTok[tid] = (slot < cnt) ? ((e < E) ? g_list[e * T + slot] : slot) : -1;
    }
    __syncthreads();

    const uint32_t sb = s2u(smem) + 1024;

    const __nv_bfloat16* Gh = (e < E) ? g_gh + (size_t)e * H * I : g_sgh;
    const __nv_bfloat16* Gl = (e < E) ? g_gl + (size_t)e * H * I : g_sgl;
    const __nv_bfloat16* Uh = (e < E) ? g_uh + (size_t)e * H * I : g_suh;
    const __nv_bfloat16* Ul = (e < E) ? g_ul + (size_t)e * H * I : g_sul;

    // A-load mapping (gather rows, 64B k-rows, SW64)
    const int u4 = tid & 3;
    const int rb = tid >> 2;
    const int tok0 = rowTok[rb];
    const int tok1 = rowTok[rb + 64];
    const size_t aG0 = (size_t)(tok0 >= 0 ? tok0 : 0) * H + u4 * 8;
    const size_t aG1 = (size_t)(tok1 >= 0 ? tok1 : 0) * H + u4 * 8;
    const uint32_t sz0 = (tok0 >= 0) ? 16u : 0u;
    const uint32_t sz1 = (tok1 >= 0) ? 16u : 0u;
    const uint32_t dA0 = SWZ64(rb * 64 + u4 * 16);
    const uint32_t dA1 = SWZ64((rb + 64) * 64 + u4 * 16);
    // B-load mapping ([32 k-rows][128B], SW128), natural [K][N] source
    const int u8 = tid & 7;
    const int rbB = tid >> 3;            // 0..31
    const size_t bGsrc = (size_t)rbB * I + n0 + u8 * 8;
    const uint32_t dB = SWZ128(rbB * 128 + u8 * 16);

    auto load_stage = [&](int st, int c) {
        const int k0 = c * 32;
        const uint32_t bp = sb + st * GU_STAGE;
        cp16(bp + GU_A_HI + dA0, g_xh + aG0 + k0, sz0);
        cp16(bp + GU_A_LO + dA0, g_xl + aG0 + k0, sz0);
        cp16(bp + GU_A_HI + dA1, g_xh + aG1 + k0, sz1);
        cp16(bp + GU_A_LO + dA1, g_xl + aG1 + k0, sz1);
        size_t bo = bGsrc + (size_t)k0 * I;
        cp16(bp + GU_BG_HI + dB, Gh + bo, 16);
        cp16(bp + GU_BG_LO + dB, Gl + bo, 16);
        cp16(bp + GU_BU_HI + dB, Uh + bo, 16);
        cp16(bp + GU_BU_LO + dB, Ul + bo, 16);
    };

    float accG[4][2][4], accU[4][2][4];
#pragma unroll
    for (int i = 0; i < 4; i++)
#pragma unroll
        for (int j = 0; j < 2; j++)
#pragma unroll
            for (int q = 0; q < 4; q++) { accG[i][j][q] = 0.f; accU[i][j][q] = 0.f; }

    const int mw = (wid & 1) * 64;
    const int nw = (wid >> 1) * 16;
    const int arow_off = ((lane >> 3) & 1) * 8 + (lane & 7);
    const int akb_off = (lane >> 4) * 16;
    // B trans-ldsm lane mapping: k_local x n_octet
    const int kloc = (lane & 7) + ((lane >> 3) & 1) * 8;
    const int noff = (lane >> 4) * 8;

    uint32_t aoff[4][2], boff[2];
#pragma unroll
    for (int i = 0; i < 4; i++)
#pragma unroll
        for (int kk = 0; kk < 2; kk++)
            aoff[i][kk] = SWZ64((mw + i * 16 + arow_off) * 64 + kk * 32 + akb_off);
#pragma unroll
    for (int kk = 0; kk < 2; kk++)
        boff[kk] = SWZ128((kk * 16 + kloc) * 128 + (nw + noff) * 2);

    auto compute_stage = [&](int st, bool doLoad, int lstage, int lc) {
        const uint32_t bp = sb + st * GU_STAGE;
#pragma unroll
        for (int kk = 0; kk < 2; kk++) {
            uint32_t a[4][4];
            uint32_t gh[4], gl[4], uh[4], ul[4];
            ldsm_x4t(gh[0], gh[1], gh[2], gh[3], bp + GU_BG_HI + boff[kk]);
            ldsm_x4t(gl[0], gl[1], gl[2], gl[3], bp + GU_BG_LO + boff[kk]);
            ldsm_x4t(uh[0], uh[1], uh[2], uh[3], bp + GU_BU_HI + boff[kk]);
            ldsm_x4t(ul[0], ul[1], ul[2], ul[3], bp + GU_BU_LO + boff[kk]);
#pragma unroll
            for (int i = 0; i < 4; i++)
                ldsm_x4(a[i][0], a[i][1], a[i][2], a[i][3], bp + GU_A_HI + aoff[i][kk]);
            if (kk == 0 && doLoad) { load_stage(lstage, lc); CP_COMMIT(); }
#pragma unroll
            for (int i = 0; i < 4; i++) {
                mma_bf16(accG[i][0], a[i], gh[0], gh[1]);
                mma_bf16(accG[i][1], a[i], gh[2], gh[3]);
                mma_bf16(accU[i][0], a[i], uh[0], uh[1]);
                mma_bf16(accU[i][1], a[i], uh[2], uh[3]);
            }
#pragma unroll
            for (int i = 0; i < 4; i++) {
                mma_bf16(accG[i][0], a[i], gl[0], gl[1]);
                mma_bf16(accG[i][1], a[i], gl[2], gl[3]);
                mma_bf16(accU[i][0], a[i], ul[0], ul[1]);
                mma_bf16(accU[i][1], a[i], ul[2], ul[3]);
            }
#pragma unroll
            for (int i = 0; i < 4; i++)
                ldsm_x4(a[i][0], a[i][1], a[i][2], a[i][3], bp + GU_A_LO + aoff[i][kk]);
#pragma unroll
            for (int i = 0; i < 4; i++) {
                mma_bf16(accG[i][0], a[i], gh[0], gh[1]);
                mma_bf16(accG[i][1], a[i], gh[2], gh[3]);
                mma_bf16(accU[i][0], a[i], uh[0], uh[1]);
                mma_bf16(accU[i][1], a[i], uh[2], uh[3]);
            }
        }
    };

    const int NC = H / 32;
    load_stage(0, 0); CP_COMMIT();
    load_stage(1, 1); CP_COMMIT();
    int st = 0;
    for (int c = 0; c < NC; c++) {
        if (c < NC - 1) CP_WAIT1(); else CP_WAIT0();
        __syncthreads();
        int ls = st + 2; if (ls >= 3) ls -= 3;
        compute_stage(st, c + 2 < NC, ls, c + 2);
        if (++st == 3) st = 0;
    }

    const int r4 = lane >> 2;
    const int cp2 = (lane & 3) * 2;
#pragma unroll
    for (int i = 0; i < 4; i++)
#pragma unroll
        for (int hh = 0; hh < 2; hh++) {
            int slot = m0 + mw + i * 16 + r4 + hh * 8;
            if (slot >= cnt) continue;
#pragma unroll
            for (int j = 0; j < 2; j++) {
                float g0 = accG[i][j][hh * 2 + 0], g1 = accG[i][j][hh * 2 + 1];
                float u0 = accU[i][j][hh * 2 + 0], u1 = accU[i][j][hh * 2 + 1];
                float v0 = g0 / (1.f + __expf(-g0)) * u0;
                float v1 = g1 / (1.f + __expf(-g1)) * u1;
                __nv_bfloat16 h0 = __float2bfloat16(v0), h1 = __float2bfloat16(v1);
                __nv_bfloat162 hp; hp.x = h0; hp.y = h1;
                __nv_bfloat162 lp;
                lp.x = __float2bfloat16(v0 - __bfloat162float(h0));
                lp.y = __float2bfloat16(v1 - __bfloat162float(h1));
                size_t ai = (size_t)e * T * I + (size_t)slot * I + n0 + nw + j * 8 + cp2;
                *reinterpret_cast<__nv_bfloat162*>(g_acth + ai) = hp;
                *reinterpret_cast<__nv_bfloat162*>(g_actl + ai) = lp;
            }
        }
}

// ======================= GEMM 2: down (fused routed+shared, N=64) ============
__global__ void __launch_bounds__(256, 2) mm_down_kernel(float* __restrict__ out) {
    extern __shared__ char smem[];
    const int ez = blockIdx.z;           // 0..7 routed, 8 shared
    const bool routed = (ez < E);
    const int cnt = routed ? g_counts[ez] : T;
    const int m0 = blockIdx.y * 128;
    if (m0 >= cnt) return;
    const int n0 = blockIdx.x * 64;
    const int tid = threadIdx.x;
    const int wid = tid >> 5;
    const int lane = tid & 31;

    int* tokSm = (int*)smem;
    float* wSm = (float*)(smem + 512);
    if (tid < 128) {
        int slot = m0 + tid;
        if (routed) {
            tokSm[tid] = (slot < cnt) ? g_list[ez * T + slot] : 0;
            wSm[tid]   = (slot < cnt) ? g_wlist[ez * T + slot] : 0.f;
        } else {
            tokSm[tid] = slot;
            wSm[tid]   = 1.f;
        }
    }
    __syncthreads();

    const uint32_t sb = s2u(smem) + 1024;

    const __nv_bfloat16* Bh = routed ? g_dh + (size_t)ez * I * H : g_sdh;
    const __nv_bfloat16* Bl = routed ? g_dl + (size_t)ez * I * H : g_sdl;
    const __nv_bfloat16* Ah = g_acth + (size_t)ez * T * I;
    const __nv_bfloat16* Al = g_actl + (size_t)ez * T * I;

    const int u4 = tid & 3;
    const int rb = tid >> 2;
    const int slot0 = m0 + rb;
    const int slot1 = m0 + rb + 64;
    const size_t aO0 = (size_t)(slot0 < cnt ? slot0 : 0) * I + u4 * 8;
    const size_t aO1 = (size_t)(slot1 < cnt ? slot1 : 0) * I + u4 * 8;
    const uint32_t sz0 = (slot0 < cnt) ? 16u : 0u;
    const uint32_t sz1 = (slot1 < cnt) ? 16u : 0u;
    const uint32_t dA0 = SWZ64(rb * 64 + u4 * 16);
    const uint32_t dA1 = SWZ64((rb + 64) * 64 + u4 * 16);
    const int u8 = tid & 7;
    const int rbB = tid >> 3;
    const size_t bSrc = (size_t)rbB * H + n0 + u8 * 8;
    const uint32_t dB = SWZ128(rbB * 128 + u8 * 16);

    auto load_stage = [&](int st, int c) {
        const int k0 = c * 32;
        const uint32_t bp = sb + st * DN_STAGE;
        cp16(bp + DN_A_HI + dA0, Ah + aO0 + k0, sz0);
        cp16(bp + DN_A_LO + dA0, Al + aO0 + k0, sz0);
        cp16(bp + DN_A_HI + dA1, Ah + aO1 + k0, sz1);
        cp16(bp + DN_A_LO + dA1, Al + aO1 + k0, sz1);
        size_t bo = bSrc + (size_t)k0 * H;
        cp16(bp + DN_B_HI + dB, Bh + bo, 16);
        cp16(bp + DN_B_LO + dB, Bl + bo, 16);
    };

    float acc[4][2][4];
#pragma unroll
    for (int i = 0; i < 4; i++)
#pragma unroll
        for (int j = 0; j < 2; j++)
#pragma unroll
            for (int q = 0; q < 4; q++) acc[i][j][q] = 0.f;

    const int mw = (wid & 1) * 64;
    const int nw = (wid >> 1) * 16;
    const int arow_off = ((lane >> 3) & 1) * 8 + (lane & 7);
    const int akb_off = (lane >> 4) * 16;
    const int kloc = (lane & 7) + ((lane >> 3) & 1) * 8;
    const int noff = (lane >> 4) * 8;

    uint32_t aoff[4][2], boff[2];
#pragma unroll
    for (int i = 0; i < 4; i++)
#pragma unroll
        for (int kk = 0; kk < 2; kk++)
            aoff[i][kk] = SWZ64((mw + i * 16 + arow_off) * 64 + kk * 32 + akb_off);
#pragma unroll
    for (int kk = 0; kk < 2; kk++)
        boff[kk] = SWZ128((kk * 16 + kloc) * 128 + (nw + noff) * 2);

    auto compute_stage = [&](int st, bool doLoad, int lstage, int lc) {
        const uint32_t bp = sb + st * DN_STAGE;
#pragma unroll
        for (int kk = 0; kk < 2; kk++) {
            uint32_t a[4][4];
            uint32_t bh[4], bl[4];
            ldsm_x4t(bh[0], bh[1], bh[2], bh[3], bp + DN_B_HI + boff[kk]);
            ldsm_x4t(bl[0], bl[1], bl[2], bl[3], bp + DN_B_LO + boff[kk]);
#pragma unroll
            for (int i = 0; i < 4; i++)
                ldsm_x4(a[i][0], a[i][1], a[i][2], a[i][3], bp + DN_A_HI + aoff[i][kk]);
            if (kk == 0 && doLoad) { load_stage(lstage, lc); CP_COMMIT(); }
#pragma unroll
            for (int i = 0; i < 4; i++) {
                mma_bf16(acc[i][0], a[i], bh[0], bh[1]);
                mma_bf16(acc[i][1], a[i], bh[2], bh[3]);
            }
#pragma unroll
            for (int i = 0; i < 4; i++) {
                mma_bf16(acc[i][0], a[i], bl[0], bl[1]);
                mma_bf16(acc[i][1], a[i], bl[2], bl[3]);
            }
#pragma unroll
            for (int i = 0; i < 4; i++)
                ldsm_x4(a[i][0], a[i][1], a[i][2], a[i][3], bp + DN_A_LO + aoff[i][kk]);
#pragma unroll
            for (int i = 0; i < 4; i++) {
                mma_bf16(acc[i][0], a[i], bh[0], bh[1]);
                mma_bf16(acc[i][1], a[i], bh[2], bh[3]);
            }
        }
    };

    const int NC = I / 32;
    load_stage(0, 0); CP_COMMIT();
    load_stage(1, 1); CP_COMMIT();
    int st = 0;
    for (int c = 0; c < NC; c++) {
        if (c < NC - 1) CP_WAIT1(); else CP_WAIT0();
        __syncthreads();
        int ls = st + 2; if (ls >= 3) ls -= 3;
        compute_stage(st, c + 2 < NC, ls, c + 2);
        if (++st == 3) st = 0;
    }

    const int r4 = lane >> 2;
    const int cp2 = (lane & 3) * 2;
#pragma unroll
    for (int i = 0; i < 4; i++)
#pragma unroll
        for (int hh = 0; hh < 2; hh++) {
            int row = mw + i * 16 + r4 + hh * 8;
            int slot = m0 + row;
            if (slot >= cnt) continue;
            int tok = tokSm[row];
            float w = wSm[row];
            float* dst = out + (size_t)tok * H;
#pragma unroll
            for (int j = 0; j < 2; j++) {
                int col = n0 + nw + j * 8 + cp2;
                atomicAdd(&dst[col],     w * acc[i][j][hh * 2 + 0]);
                atomicAdd(&dst[col + 1], w * acc[i][j][hh * 2 + 1]);
            }
        }
}

// ======================= launch =============================================
extern "C" void kernel_launch(void* const* d_in, const int* in_sizes, int n_in,
                              void* d_out, int out_size) {
    const float* x   = (const float*)d_in[0];
    const float* rw  = (const float*)d_in[1];
    const float* gw  = (const float*)d_in[2];
    const float* uw  = (const float*)d_in[3];
    const float* dw  = (const float*)d_in[4];
    const float* sgw = (const float*)d_in[5];
    const float* suw = (const float*)d_in[6];
    const float* sdw = (const float*)d_in[7];
    float* out = (float*)d_out;

    cudaFuncSetAttribute(mm_gateup_kernel,
                         cudaFuncAttributeMaxDynamicSharedMemorySize, GU_SMEM);
    cudaFuncSetAttribute(mm_down_kernel,
                         cudaFuncAttributeMaxDynamicSharedMemorySize, DN_SMEM);

    init_kernel<<<1, 32>>>();
    prep_kernel<<<NROUTER + NWBLK, 256>>>(x, rw, gw, uw, dw, sgw, suw, sdw, out);
    mm_gateup_kernel<<<dim3(I / 64, T / 128, E + 1), 256, GU_SMEM>>>();
    mm_down_kernel<<<dim3(H / 64, T / 128, E + 1), 256, DN_SMEM>>>(out);
    finalize_kernel<<<1, 32>>>(out);
}